// round 1
// baseline (speedup 1.0000x reference)
#include <cuda_runtime.h>
#include <cstdint>

#define BB 1024
#define TT 256
#define DD 64
#define HH 128

// Scratch: precomputed input-side affine terms (bias included).
// Gx[b,t,j] = x[b,t]@gate_kernel[0:64] + gate_bias   (j < 256)
// Cx[b,t,j] = x[b,t]@cand_kernel[0:64] + cand_bias   (j < 128)
__device__ float g_Gx[(size_t)BB * TT * 2 * HH];   // 268 MB
__device__ float g_Cx[(size_t)BB * TT * HH];       // 134 MB

__device__ __forceinline__ float fast_sigmoid(float x) {
    return __fdividef(1.0f, 1.0f + __expf(-x));
}
__device__ __forceinline__ float fast_tanh(float x) {
    return __fdividef(2.0f, 1.0f + __expf(-2.0f * x)) - 1.0f;
}

// ---------------------------------------------------------------------------
// Kernel 1: gather x = emb[item] and compute input-side GEMMs for 16 t's of
// one batch row per block. Skips chunks entirely past seq_len.
// 256 threads. Thread tile: 4 t-rows x 6 cols (cols strided by 64).
// ---------------------------------------------------------------------------
#define XPRE_SMEM ((64 * 20 + 64 * 384) * 4)

__global__ void xpre_kernel(const int* __restrict__ item,
                            const int* __restrict__ lens,
                            const float* __restrict__ emb,
                            const float* __restrict__ gk,
                            const float* __restrict__ gb,
                            const float* __restrict__ ck,
                            const float* __restrict__ cb) {
    extern __shared__ float s[];
    float* xs = s;              // [64][20]  (x transposed: [d][t], padded)
    float* Ws = s + 64 * 20;    // [64][384] combined gate|cand input weights

    const int b  = blockIdx.y;
    const int t0 = blockIdx.x * 16;
    const int len = lens[b];
    if (t0 >= len) return;      // uniform per block

    const int tid = threadIdx.x;

    // Load combined input-side weights into smem
    for (int idx = tid; idx < 64 * 384; idx += 256) {
        const int k = idx / 384, j = idx - k * 384;
        Ws[idx] = (j < 256) ? gk[k * 256 + j] : ck[k * 128 + (j - 256)];
    }
    // Gather 16 x-rows, store transposed
    {
        const int trow = tid >> 4;          // 0..15
        const int dg   = tid & 15;          // 0..15 (4 floats each)
        const int t    = t0 + trow;
        const int id   = item[b * TT + t];
        const float4 v = *(const float4*)(emb + (size_t)id * 64 + dg * 4);
        xs[(dg * 4 + 0) * 20 + trow] = v.x;
        xs[(dg * 4 + 1) * 20 + trow] = v.y;
        xs[(dg * 4 + 2) * 20 + trow] = v.z;
        xs[(dg * 4 + 3) * 20 + trow] = v.w;
    }
    __syncthreads();

    const int rg = tid >> 6;        // 0..3  -> t-rows r0..r0+3
    const int cg = tid & 63;        // 0..63 -> cols cg + 64*i
    const int r0 = rg * 4;

    float acc[4][6];
#pragma unroll
    for (int i = 0; i < 6; i++) {
        const int j = cg + 64 * i;
        const float bias = (j < 256) ? gb[j] : cb[j - 256];
        acc[0][i] = bias; acc[1][i] = bias; acc[2][i] = bias; acc[3][i] = bias;
    }

#pragma unroll 8
    for (int k = 0; k < 64; k++) {
        const float4 xv = *(const float4*)&xs[k * 20 + r0];
#pragma unroll
        for (int i = 0; i < 6; i++) {
            const float w = Ws[k * 384 + cg + 64 * i];
            acc[0][i] += xv.x * w;
            acc[1][i] += xv.y * w;
            acc[2][i] += xv.z * w;
            acc[3][i] += xv.w * w;
        }
    }

#pragma unroll
    for (int ii = 0; ii < 4; ii++) {
        const size_t row = (size_t)(b * TT + (t0 + r0 + ii));
#pragma unroll
        for (int i = 0; i < 6; i++) {
            const int j = cg + 64 * i;
            if (j < 256) g_Gx[(row << 8) + j]          = acc[ii][i];
            else         g_Cx[(row << 7) + (j - 256)]  = acc[ii][i];
        }
    }
}

// ---------------------------------------------------------------------------
// Kernel 2: persistent GRU recurrence. 128 blocks x 8 batch rows, 128 threads.
// All h-side weights in SMEM (fp32). h kept k-major in SMEM: hs[k][r].
// Per step: Phase A (gates, K=128 -> 256 cols), Phase B (candidate, 128 cols).
// ---------------------------------------------------------------------------
#define GRU_SMEM ((128 * 256 + 128 * 128 + 128 * 8 + 128 * 8 + 8 * 128) * 4)

__global__ void gru_kernel(const int* __restrict__ lens,
                           const float* __restrict__ gk,
                           const float* __restrict__ ck,
                           float* __restrict__ out) {
    extern __shared__ float s[];
    float* Wg  = s;                       // [128][256] gate h-weights
    float* Wc  = Wg + 128 * 256;          // [128][128] cand h-weights
    float* hs  = Wc + 128 * 128;          // [128][8]   h, k-major
    float* rhs = hs + 128 * 8;            // [128][8]   r*h, k-major
    float* us  = rhs + 128 * 8;           // [8][128]   u-gate, row-major

    const int tid = threadIdx.x;
    const int bl  = blockIdx.x;

    for (int idx = tid; idx < 128 * 256; idx += 128) {
        const int k = idx >> 8, j = idx & 255;
        Wg[idx] = gk[(64 + k) * 256 + j];
    }
    for (int idx = tid; idx < 128 * 128; idx += 128) {
        const int k = idx >> 7, j = idx & 127;
        Wc[idx] = ck[(64 + k) * 128 + j];
    }
    for (int idx = tid; idx < 128 * 8; idx += 128) hs[idx] = 0.0f;

    const int rg  = tid >> 6;     // 0..1
    const int cg  = tid & 63;     // 0..63
    const int r0  = rg * 4;
    const int j0  = cg * 4;       // Phase A col base (0..252)
    const int jb0 = cg * 2;       // Phase B col base (0..126)

    int maxlen = 0;
#pragma unroll
    for (int r = 0; r < 8; r++) {
        const int l = lens[bl * 8 + r];
        maxlen = max(maxlen, l);
    }
    int len4[4];
#pragma unroll
    for (int i = 0; i < 4; i++) len4[i] = lens[bl * 8 + r0 + i];

    __syncthreads();

    for (int t = 0; t < maxlen; t++) {
        // Prefetch input-side terms for this step (lands during Phase A loop)
        float4 gx[4];
        float2 cxv[4];
#pragma unroll
        for (int i = 0; i < 4; i++) {
            const size_t row = (size_t)((bl * 8 + r0 + i) * TT + t);
            gx[i]  = *(const float4*)&g_Gx[(row << 8) + j0];
            cxv[i] = *(const float2*)&g_Cx[(row << 7) + jb0];
        }

        // ---- Phase A: a[r][j] = h @ Wg_h, j in [j0, j0+4) ----
        float acc[4][4];
#pragma unroll
        for (int i = 0; i < 4; i++)
            acc[i][0] = acc[i][1] = acc[i][2] = acc[i][3] = 0.0f;

#pragma unroll 8
        for (int k = 0; k < 128; k++) {
            const float4 hv = *(const float4*)&hs[k * 8 + r0];   // broadcast
            const float4 wv = *(const float4*)&Wg[k * 256 + j0]; // coalesced
            acc[0][0] += hv.x * wv.x; acc[0][1] += hv.x * wv.y;
            acc[0][2] += hv.x * wv.z; acc[0][3] += hv.x * wv.w;
            acc[1][0] += hv.y * wv.x; acc[1][1] += hv.y * wv.y;
            acc[1][2] += hv.y * wv.z; acc[1][3] += hv.y * wv.w;
            acc[2][0] += hv.z * wv.x; acc[2][1] += hv.z * wv.y;
            acc[2][2] += hv.z * wv.z; acc[2][3] += hv.z * wv.w;
            acc[3][0] += hv.w * wv.x; acc[3][1] += hv.w * wv.y;
            acc[3][2] += hv.w * wv.z; acc[3][3] += hv.w * wv.w;
        }

        float sg[4][4];
#pragma unroll
        for (int i = 0; i < 4; i++) {
            sg[i][0] = fast_sigmoid(acc[i][0] + gx[i].x);
            sg[i][1] = fast_sigmoid(acc[i][1] + gx[i].y);
            sg[i][2] = fast_sigmoid(acc[i][2] + gx[i].z);
            sg[i][3] = fast_sigmoid(acc[i][3] + gx[i].w);
        }

        if (cg < 32) {
            // r-gate (j0 < 128): write r*h into rhs (k-major)
#pragma unroll
            for (int jj = 0; jj < 4; jj++) {
                const int j = j0 + jj;
                const float4 hv = *(const float4*)&hs[j * 8 + r0];
                float4 rv;
                rv.x = sg[0][jj] * hv.x;
                rv.y = sg[1][jj] * hv.y;
                rv.z = sg[2][jj] * hv.z;
                rv.w = sg[3][jj] * hv.w;
                *(float4*)&rhs[j * 8 + r0] = rv;
            }
        } else {
            // u-gate (j0 >= 128): stash into us row-major
#pragma unroll
            for (int i = 0; i < 4; i++) {
                float4 uv;
                uv.x = sg[i][0]; uv.y = sg[i][1]; uv.z = sg[i][2]; uv.w = sg[i][3];
                *(float4*)&us[(r0 + i) * 128 + (j0 - 128)] = uv;
            }
        }
        __syncthreads();

        // ---- Phase B: c[r][j] = (r*h) @ Wc_h, j in [jb0, jb0+2) ----
        float cac[4][2];
#pragma unroll
        for (int i = 0; i < 4; i++) { cac[i][0] = 0.0f; cac[i][1] = 0.0f; }

#pragma unroll 8
        for (int k = 0; k < 128; k++) {
            const float4 rv = *(const float4*)&rhs[k * 8 + r0];  // broadcast
            const float2 wv = *(const float2*)&Wc[k * 128 + jb0];
            cac[0][0] += rv.x * wv.x; cac[0][1] += rv.x * wv.y;
            cac[1][0] += rv.y * wv.x; cac[1][1] += rv.y * wv.y;
            cac[2][0] += rv.z * wv.x; cac[2][1] += rv.z * wv.y;
            cac[3][0] += rv.w * wv.x; cac[3][1] += rv.w * wv.y;
        }

#pragma unroll
        for (int jj = 0; jj < 2; jj++) {
            const int j = jb0 + jj;
            float4 hold = *(const float4*)&hs[j * 8 + r0];
            float cx0, cx1, cx2, cx3;
            cx0 = (jj == 0) ? cxv[0].x : cxv[0].y;
            cx1 = (jj == 0) ? cxv[1].x : cxv[1].y;
            cx2 = (jj == 0) ? cxv[2].x : cxv[2].y;
            cx3 = (jj == 0) ? cxv[3].x : cxv[3].y;

            const float c0 = fast_tanh(cac[0][jj] + cx0);
            const float c1 = fast_tanh(cac[1][jj] + cx1);
            const float c2 = fast_tanh(cac[2][jj] + cx2);
            const float c3 = fast_tanh(cac[3][jj] + cx3);

            const float u0 = us[(r0 + 0) * 128 + j];
            const float u1 = us[(r0 + 1) * 128 + j];
            const float u2 = us[(r0 + 2) * 128 + j];
            const float u3 = us[(r0 + 3) * 128 + j];

            const float h0 = u0 * hold.x + (1.0f - u0) * c0;
            const float h1 = u1 * hold.y + (1.0f - u1) * c1;
            const float h2 = u2 * hold.z + (1.0f - u2) * c2;
            const float h3 = u3 * hold.w + (1.0f - u3) * c3;

            hold.x = (t < len4[0]) ? h0 : hold.x;
            hold.y = (t < len4[1]) ? h1 : hold.y;
            hold.z = (t < len4[2]) ? h2 : hold.z;
            hold.w = (t < len4[3]) ? h3 : hold.w;

            *(float4*)&hs[j * 8 + r0] = hold;
        }
        __syncthreads();
    }

    // Write final h (also covers maxlen==0 -> zeros)
    for (int idx = tid; idx < 8 * 128; idx += 128) {
        const int r = idx >> 7, j = idx & 127;
        out[(size_t)(bl * 8 + r) * 128 + j] = hs[j * 8 + r];
    }
}

// ---------------------------------------------------------------------------
extern "C" void kernel_launch(void* const* d_in, const int* in_sizes, int n_in,
                              void* d_out, int out_size) {
    const int*   item = (const int*)d_in[0];
    const int*   lens = (const int*)d_in[1];
    const float* emb  = (const float*)d_in[2];
    const float* gk   = (const float*)d_in[3];
    const float* gb   = (const float*)d_in[4];
    const float* ck   = (const float*)d_in[5];
    const float* cb   = (const float*)d_in[6];
    float* out = (float*)d_out;

    cudaFuncSetAttribute(xpre_kernel, cudaFuncAttributeMaxDynamicSharedMemorySize, XPRE_SMEM);
    cudaFuncSetAttribute(gru_kernel,  cudaFuncAttributeMaxDynamicSharedMemorySize, GRU_SMEM);

    xpre_kernel<<<dim3(TT / 16, BB), 256, XPRE_SMEM>>>(item, lens, emb, gk, gb, ck, cb);
    gru_kernel<<<BB / 8, 128, GRU_SMEM>>>(lens, gk, ck, out);
}

// round 5
// speedup vs baseline: 1.2550x; 1.2550x over previous
#include <cuda_runtime.h>
#include <cstdint>

#define BB 1024
#define TT 256
#define DD 64
#define HH 128

// Scratch: precomputed input-side affine terms (bias included).
__device__ float g_Gx[(size_t)BB * TT * 2 * HH];   // 268 MB
__device__ float g_Cx[(size_t)BB * TT * HH];       // 134 MB

__device__ __forceinline__ float fast_sigmoid(float x) {
    return __fdividef(1.0f, 1.0f + __expf(-x));
}
__device__ __forceinline__ float fast_tanh(float x) {
    return __fdividef(2.0f, 1.0f + __expf(-2.0f * x)) - 1.0f;
}

// Packed fp32x2 helpers (sm_103a FFMA2)
typedef unsigned long long u64;
__device__ __forceinline__ u64 ffma2(u64 a, u64 b, u64 c) {
    u64 d;
    asm("fma.rn.f32x2 %0, %1, %2, %3;" : "=l"(d) : "l"(a), "l"(b), "l"(c));
    return d;
}
__device__ __forceinline__ u64 pack2(float lo, float hi) {
    u64 d; asm("mov.b64 %0, {%1, %2};" : "=l"(d) : "f"(lo), "f"(hi)); return d;
}
__device__ __forceinline__ float2 unpack2(u64 v) {
    float lo, hi; asm("mov.b64 {%0, %1}, %2;" : "=f"(lo), "=f"(hi) : "l"(v));
    return make_float2(lo, hi);
}

// ---------------------------------------------------------------------------
// Kernel 1: gather x = emb[item]; input-side GEMM for 16 t's of one batch row.
// 256 threads. f32x2 col-pair packing: thread tile = 4 t-rows x 3 col-pairs.
// cols: j = cg*2 + 128*i  (i=0,1 -> Gx; i=2 -> Cx)
// ---------------------------------------------------------------------------
#define XPRE_SMEM ((64 * 20 + 64 * 384) * 4)

__global__ __launch_bounds__(256) void xpre_kernel(
        const int* __restrict__ item,
        const int* __restrict__ lens,
        const float* __restrict__ emb,
        const float* __restrict__ gk,
        const float* __restrict__ gb,
        const float* __restrict__ ck,
        const float* __restrict__ cb) {
    extern __shared__ float s[];
    float* xs = s;              // [64][20]  x transposed [d][t]
    float* Ws = s + 64 * 20;    // [64][384] gate|cand input weights

    const int b  = blockIdx.y;
    const int t0 = blockIdx.x * 16;
    const int len = lens[b];
    if (t0 >= len) return;

    const int tid = threadIdx.x;

    for (int idx = tid; idx < 64 * 384; idx += 256) {
        const int k = idx / 384, j = idx - k * 384;
        Ws[idx] = (j < 256) ? gk[k * 256 + j] : ck[k * 128 + (j - 256)];
    }
    {
        const int trow = tid >> 4;
        const int dg   = tid & 15;
        const int t    = t0 + trow;
        const int id   = item[b * TT + t];
        const float4 v = *(const float4*)(emb + (size_t)id * 64 + dg * 4);
        xs[(dg * 4 + 0) * 20 + trow] = v.x;
        xs[(dg * 4 + 1) * 20 + trow] = v.y;
        xs[(dg * 4 + 2) * 20 + trow] = v.z;
        xs[(dg * 4 + 3) * 20 + trow] = v.w;
    }
    __syncthreads();

    const int rg = tid >> 6;        // 0..3 -> t-rows r0..r0+3
    const int cg = tid & 63;        // col-pair base
    const int r0 = rg * 4;

    u64 acc[4][3];
#pragma unroll
    for (int i = 0; i < 3; i++) {
        const int j = cg * 2 + 128 * i;
        float b0, b1;
        if (j < 256) { b0 = gb[j]; b1 = gb[j + 1]; }
        else         { b0 = cb[j - 256]; b1 = cb[j - 255]; }
        const u64 bp = pack2(b0, b1);
        acc[0][i] = bp; acc[1][i] = bp; acc[2][i] = bp; acc[3][i] = bp;
    }

#pragma unroll 8
    for (int k = 0; k < 64; k++) {
        const float4 xv = *(const float4*)&xs[k * 20 + r0];
        const u64 xd0 = pack2(xv.x, xv.x);
        const u64 xd1 = pack2(xv.y, xv.y);
        const u64 xd2 = pack2(xv.z, xv.z);
        const u64 xd3 = pack2(xv.w, xv.w);
        const float* wrow = &Ws[k * 384 + cg * 2];
#pragma unroll
        for (int i = 0; i < 3; i++) {
            const float2 wv = *(const float2*)(wrow + 128 * i);
            const u64 wp = pack2(wv.x, wv.y);
            acc[0][i] = ffma2(xd0, wp, acc[0][i]);
            acc[1][i] = ffma2(xd1, wp, acc[1][i]);
            acc[2][i] = ffma2(xd2, wp, acc[2][i]);
            acc[3][i] = ffma2(xd3, wp, acc[3][i]);
        }
    }

#pragma unroll
    for (int ii = 0; ii < 4; ii++) {
        const size_t row = (size_t)(b * TT + (t0 + r0 + ii));
#pragma unroll
        for (int i = 0; i < 3; i++) {
            const int j = cg * 2 + 128 * i;
            const float2 v = unpack2(acc[ii][i]);
            if (i < 2) *(float2*)&g_Gx[(row << 8) + j]         = v;
            else       *(float2*)&g_Cx[(row << 7) + (j - 256)] = v;
        }
    }
}

// ---------------------------------------------------------------------------
// Kernel 2: persistent GRU recurrence, f32x2 over batch-row pairs.
// 128 blocks x 8 batch rows, 128 threads.
// Phase A: thread owns 2 gate cols (j0 = tid*2), all 8 rows (4 row-pairs).
// Phase B: thread owns 1 cand col (jb = tid), all 8 rows.
// ---------------------------------------------------------------------------
#define GRU_SMEM ((128 * 256 + 128 * 128 + 3 * 128 * 8) * 4)

__global__ __launch_bounds__(128, 1) void gru_kernel(
        const int* __restrict__ lens,
        const float* __restrict__ gk,
        const float* __restrict__ ck,
        float* __restrict__ out) {
    extern __shared__ float s[];
    float* Wg  = s;                       // [128][256]
    float* Wc  = Wg + 128 * 256;          // [128][128]
    float* hs  = Wc + 128 * 128;          // [128][8]  h, k-major
    float* rhs = hs + 128 * 8;            // [128][8]  r*h, k-major
    float* us  = rhs + 128 * 8;           // [128][8]  u, col-major [j][r]

    const int tid = threadIdx.x;
    const int bl  = blockIdx.x;

    for (int idx = tid; idx < 128 * 256; idx += 128) {
        const int k = idx >> 8, j = idx & 255;
        Wg[idx] = gk[(64 + k) * 256 + j];
    }
    for (int idx = tid; idx < 128 * 128; idx += 128) {
        const int k = idx >> 7, j = idx & 127;
        Wc[idx] = ck[(64 + k) * 128 + j];
    }
    for (int idx = tid; idx < 128 * 8; idx += 128) hs[idx] = 0.0f;

    const int j0 = tid * 2;   // Phase A col base (0..254)
    const int jb = tid;       // Phase B col

    int len8[8];
    int maxlen = 0;
#pragma unroll
    for (int r = 0; r < 8; r++) {
        len8[r] = lens[bl * 8 + r];
        maxlen = max(maxlen, len8[r]);
    }
    __syncthreads();

    for (int t = 0; t < maxlen; t++) {
        // Prefetch input-side gate terms for the 8 rows
        float2 gx[8];
#pragma unroll
        for (int r = 0; r < 8; r++) {
            const size_t row = (size_t)((bl * 8 + r) * TT + t);
            gx[r] = *(const float2*)&g_Gx[(row << 8) + j0];
        }

        // ---- Phase A: a[r][c] = h @ Wg_h ----
        u64 acc[4][2];
#pragma unroll
        for (int p = 0; p < 4; p++) { acc[p][0] = 0ull; acc[p][1] = 0ull; }

#pragma unroll 8
        for (int k = 0; k < 128; k++) {
            const float4 hA = *(const float4*)&hs[k * 8];     // rows 0-3 (bcast)
            const float4 hB = *(const float4*)&hs[k * 8 + 4]; // rows 4-7
            const u64 hp0 = pack2(hA.x, hA.y);
            const u64 hp1 = pack2(hA.z, hA.w);
            const u64 hp2 = pack2(hB.x, hB.y);
            const u64 hp3 = pack2(hB.z, hB.w);
            const float2 wv = *(const float2*)&Wg[k * 256 + j0];
            const u64 wd0 = pack2(wv.x, wv.x);
            const u64 wd1 = pack2(wv.y, wv.y);
            acc[0][0] = ffma2(hp0, wd0, acc[0][0]);
            acc[1][0] = ffma2(hp1, wd0, acc[1][0]);
            acc[2][0] = ffma2(hp2, wd0, acc[2][0]);
            acc[3][0] = ffma2(hp3, wd0, acc[3][0]);
            acc[0][1] = ffma2(hp0, wd1, acc[0][1]);
            acc[1][1] = ffma2(hp1, wd1, acc[1][1]);
            acc[2][1] = ffma2(hp2, wd1, acc[2][1]);
            acc[3][1] = ffma2(hp3, wd1, acc[3][1]);
        }

        // sigmoid(acc + gx):  sg[r][c]
        float sg[8][2];
#pragma unroll
        for (int p = 0; p < 4; p++) {
#pragma unroll
            for (int c = 0; c < 2; c++) {
                const float2 a = unpack2(acc[p][c]);
                const float g0 = (c == 0) ? gx[2 * p].x     : gx[2 * p].y;
                const float g1 = (c == 0) ? gx[2 * p + 1].x : gx[2 * p + 1].y;
                sg[2 * p][c]     = fast_sigmoid(a.x + g0);
                sg[2 * p + 1][c] = fast_sigmoid(a.y + g1);
            }
        }

        if (tid < 64) {
            // r-gate: j0 in [0,128). Write r*h (k-major) for cols j0, j0+1.
#pragma unroll
            for (int c = 0; c < 2; c++) {
                const int j = j0 + c;
                const float4 hA = *(const float4*)&hs[j * 8];
                const float4 hB = *(const float4*)&hs[j * 8 + 4];
                float4 rA, rB;
                rA.x = sg[0][c] * hA.x; rA.y = sg[1][c] * hA.y;
                rA.z = sg[2][c] * hA.z; rA.w = sg[3][c] * hA.w;
                rB.x = sg[4][c] * hB.x; rB.y = sg[5][c] * hB.y;
                rB.z = sg[6][c] * hB.z; rB.w = sg[7][c] * hB.w;
                *(float4*)&rhs[j * 8]     = rA;
                *(float4*)&rhs[j * 8 + 4] = rB;
            }
        } else {
            // u-gate: j0 in [128,256) -> h-col jc = j0-128. Store us[jc][r].
#pragma unroll
            for (int c = 0; c < 2; c++) {
                const int jc = j0 - 128 + c;
                float4 uA, uB;
                uA.x = sg[0][c]; uA.y = sg[1][c]; uA.z = sg[2][c]; uA.w = sg[3][c];
                uB.x = sg[4][c]; uB.y = sg[5][c]; uB.z = sg[6][c]; uB.w = sg[7][c];
                *(float4*)&us[jc * 8]     = uA;
                *(float4*)&us[jc * 8 + 4] = uB;
            }
        }
        __syncthreads();

        // Prefetch input-side candidate terms
        float cx[8];
#pragma unroll
        for (int r = 0; r < 8; r++) {
            const size_t row = (size_t)((bl * 8 + r) * TT + t);
            cx[r] = g_Cx[(row << 7) + jb];
        }

        // ---- Phase B: c[r] = (r*h) @ Wc_h, col jb ----
        u64 cac[4];
#pragma unroll
        for (int p = 0; p < 4; p++) cac[p] = 0ull;

#pragma unroll 8
        for (int k = 0; k < 128; k++) {
            const float4 rA = *(const float4*)&rhs[k * 8];
            const float4 rB = *(const float4*)&rhs[k * 8 + 4];
            const u64 rp0 = pack2(rA.x, rA.y);
            const u64 rp1 = pack2(rA.z, rA.w);
            const u64 rp2 = pack2(rB.x, rB.y);
            const u64 rp3 = pack2(rB.z, rB.w);
            const float w = Wc[k * 128 + jb];
            const u64 wd = pack2(w, w);
            cac[0] = ffma2(rp0, wd, cac[0]);
            cac[1] = ffma2(rp1, wd, cac[1]);
            cac[2] = ffma2(rp2, wd, cac[2]);
            cac[3] = ffma2(rp3, wd, cac[3]);
        }

        // h update for col jb, all 8 rows
        {
            float cpre[8];
#pragma unroll
            for (int p = 0; p < 4; p++) {
                const float2 v = unpack2(cac[p]);
                cpre[2 * p] = v.x; cpre[2 * p + 1] = v.y;
            }
            float4 hA = *(const float4*)&hs[jb * 8];
            float4 hB = *(const float4*)&hs[jb * 8 + 4];
            const float4 uA = *(const float4*)&us[jb * 8];
            const float4 uB = *(const float4*)&us[jb * 8 + 4];
            float hn[8];
            hn[0] = uA.x * hA.x + (1.0f - uA.x) * fast_tanh(cpre[0] + cx[0]);
            hn[1] = uA.y * hA.y + (1.0f - uA.y) * fast_tanh(cpre[1] + cx[1]);
            hn[2] = uA.z * hA.z + (1.0f - uA.z) * fast_tanh(cpre[2] + cx[2]);
            hn[3] = uA.w * hA.w + (1.0f - uA.w) * fast_tanh(cpre[3] + cx[3]);
            hn[4] = uB.x * hB.x + (1.0f - uB.x) * fast_tanh(cpre[4] + cx[4]);
            hn[5] = uB.y * hB.y + (1.0f - uB.y) * fast_tanh(cpre[5] + cx[5]);
            hn[6] = uB.z * hB.z + (1.0f - uB.z) * fast_tanh(cpre[6] + cx[6]);
            hn[7] = uB.w * hB.w + (1.0f - uB.w) * fast_tanh(cpre[7] + cx[7]);
            hA.x = (t < len8[0]) ? hn[0] : hA.x;
            hA.y = (t < len8[1]) ? hn[1] : hA.y;
            hA.z = (t < len8[2]) ? hn[2] : hA.z;
            hA.w = (t < len8[3]) ? hn[3] : hA.w;
            hB.x = (t < len8[4]) ? hn[4] : hB.x;
            hB.y = (t < len8[5]) ? hn[5] : hB.y;
            hB.z = (t < len8[6]) ? hn[6] : hB.z;
            hB.w = (t < len8[7]) ? hn[7] : hB.w;
            *(float4*)&hs[jb * 8]     = hA;
            *(float4*)&hs[jb * 8 + 4] = hB;
        }
        __syncthreads();
    }

    for (int idx = tid; idx < 8 * 128; idx += 128) {
        const int r = idx >> 7, j = idx & 127;
        out[(size_t)(bl * 8 + r) * 128 + j] = hs[j * 8 + r];
    }
}

// ---------------------------------------------------------------------------
extern "C" void kernel_launch(void* const* d_in, const int* in_sizes, int n_in,
                              void* d_out, int out_size) {
    const int*   item = (const int*)d_in[0];
    const int*   lens = (const int*)d_in[1];
    const float* emb  = (const float*)d_in[2];
    const float* gk   = (const float*)d_in[3];
    const float* gb   = (const float*)d_in[4];
    const float* ck   = (const float*)d_in[5];
    const float* cb   = (const float*)d_in[6];
    float* out = (float*)d_out;

    cudaFuncSetAttribute(xpre_kernel, cudaFuncAttributeMaxDynamicSharedMemorySize, XPRE_SMEM);
    cudaFuncSetAttribute(gru_kernel,  cudaFuncAttributeMaxDynamicSharedMemorySize, GRU_SMEM);

    xpre_kernel<<<dim3(TT / 16, BB), 256, XPRE_SMEM>>>(item, lens, emb, gk, gb, ck, cb);
    gru_kernel<<<BB / 8, 128, GRU_SMEM>>>(lens, gk, ck, out);
}